// round 13
// baseline (speedup 1.0000x reference)
#include <cuda_runtime.h>
#include <cuda_fp16.h>

#define NN 4096
#define FIN 128
#define FOUT 64
#define HEADS 4
#define MSPLIT 4
#define RPB 128          // n-rows per block in k_attn
#define MTILE 128        // m per smem tile
#define HSTRIDE 136      // halves per HsT row (128 + 8 pad -> LDSM conflict-free)

// Device scratch (allocation-free rule: __device__ globals)
__device__ __half   g_HT[HEADS * FOUT * NN];         // H transposed: [h][o][m] fp16
__device__ float2   g_EF[HEADS * NN];                // {exp(d), exp(0.01d)}
__device__ float    g_G[HEADS * NN];                 // exp(-0.99 s)
__device__ unsigned g_mask[NN * (NN / 32)];          // bit-packed A|diag, MMA-permuted
__device__ unsigned g_numh[HEADS * MSPLIT * NN * (FOUT / 2)];  // fp16x2, scaled 1/32
__device__ float    g_l[HEADS * MSPLIT * NN];

__device__ __forceinline__ unsigned hmul2u(unsigned a, unsigned b) {
    __half2 r = __hmul2(*(__half2*)&a, *(__half2*)&b);
    return *(unsigned*)&r;
}
__device__ __forceinline__ unsigned hmax2u(unsigned a, unsigned b) {
    __half2 r = __hmax2(*(__half2*)&a, *(__half2*)&b);
    return *(unsigned*)&r;
}
__device__ __forceinline__ unsigned pk2(float lo, float hi) {
    __half2 r = __floats2half2_rn(lo, hi);
    return *(unsigned*)&r;
}
__device__ __forceinline__ unsigned smem_u32(const void* p) {
    return (unsigned)__cvta_generic_to_shared(p);
}

__device__ __forceinline__ void mma_f16(float c[4], const unsigned a[4],
                                        unsigned b0, unsigned b1) {
    asm volatile(
        "mma.sync.aligned.m16n8k16.row.col.f32.f16.f16.f32 "
        "{%0,%1,%2,%3}, {%4,%5,%6,%7}, {%8,%9}, {%0,%1,%2,%3};\n"
        : "+f"(c[0]), "+f"(c[1]), "+f"(c[2]), "+f"(c[3])
        : "r"(a[0]), "r"(a[1]), "r"(a[2]), "r"(a[3]), "r"(b0), "r"(b1));
}

// ---------------------------------------------------------------------------
// Kernel 1: merged projection (blocks 0..255) + adjacency bit-pack (blocks
// 256..1279, 4 rows each). Pack front-batches 16 independent LDG.128 per
// thread (8 KB in flight per warp) BEFORE any REDUX consumes them -> the
// DRAM pipe stays full. A in {0,1}: value IS the bit (3 IMAD + shift).
// Diagonal OR'd scalar-side at store. Bit layout identical to prior rounds:
// word bit (16hh+4tt+dd) = adjacency col (16hh + 2tt + (dd&1) + 8*(dd>>1)).
// ---------------------------------------------------------------------------
__global__ void __launch_bounds__(256) k_pp(const int* __restrict__ A,
                                            const float* __restrict__ X,
                                            const float* __restrict__ W,
                                            const float* __restrict__ b,
                                            const float* __restrict__ att) {
    __shared__ __align__(16) float XsT[64][68];   // [k][n-row]
    __shared__ __align__(16) float WsT[64][68];   // [k][o-row]
    const int t = threadIdx.x;

    if (blockIdx.x >= 256) {
        const int rowBase = (blockIdx.x - 256) * 4;
        const int warp = t >> 5, lane = t & 31;
        const int j    = lane & 7;
        const int w    = lane >> 3;
        const int base = 16 * (j >> 2) + 8 * (j & 1) + 2 * ((j >> 1) & 1);
        const unsigned submask = 0xFFu << (w << 3);

        // front-batch ALL 16 loads (4 rows x 4 chunks) -> MLP=16
        int4 a4[16];
#pragma unroll
        for (int r = 0; r < 4; r++)
#pragma unroll
            for (int it = 0; it < 4; it++)
                a4[r * 4 + it] = *(const int4*)&A[(rowBase + r) * NN
                                                  + (it * 8 + warp) * 128 + lane * 4];

#pragma unroll
        for (int r = 0; r < 4; r++) {
            const int row = rowBase + r;
#pragma unroll
            for (int it = 0; it < 4; it++) {
                const int4 v = a4[r * 4 + it];
                const int chunk = it * 8 + warp;
                unsigned v01 = (unsigned)v.x + ((unsigned)v.y << 1);
                unsigned v23 = (unsigned)v.z + ((unsigned)v.w << 1);
                unsigned contrib = (v01 + (v23 << 4)) << base;
                unsigned word = __reduce_or_sync(submask, contrib);
                if (j == 0) {
                    const int widx = chunk * 4 + w;
                    if (widx == (row >> 5)) {      // diagonal lives in this word
                        const int c = row & 31;
                        word |= 1u << (16 * (c >> 4) + 4 * ((c & 7) >> 1)
                                       + 2 * ((c >> 3) & 1) + (c & 1));
                    }
                    g_mask[row * (NN / 32) + widx] = word;
                }
            }
        }
        return;
    }

    // ---------------- projection + fused scores/exp factors ----------------
    const int h  = blockIdx.x >> 6;
    const int n0 = (blockIdx.x & 63) * 64;
    const int ty = t >> 4, tx = t & 15;

    float acc[4][4] = {};

    for (int kc = 0; kc < FIN; kc += 64) {
        __syncthreads();
#pragma unroll
        for (int u = 0; u < 4; u++) {
            int idx = t + 256 * u;
            int r = idx >> 4, q = (idx & 15) * 4;
            float4 xv = *(const float4*)&X[(n0 + r) * FIN + kc + q];
            XsT[q + 0][r] = xv.x; XsT[q + 1][r] = xv.y;
            XsT[q + 2][r] = xv.z; XsT[q + 3][r] = xv.w;
            float4 wv = *(const float4*)&W[(h * FOUT + r) * FIN + kc + q];
            WsT[q + 0][r] = wv.x; WsT[q + 1][r] = wv.y;
            WsT[q + 2][r] = wv.z; WsT[q + 3][r] = wv.w;
        }
        __syncthreads();
#pragma unroll 8
        for (int k = 0; k < 64; k++) {
            float4 av = *(const float4*)&XsT[k][ty * 4];
            float4 bv = *(const float4*)&WsT[k][tx * 4];
            acc[0][0] += av.x * bv.x; acc[0][1] += av.x * bv.y; acc[0][2] += av.x * bv.z; acc[0][3] += av.x * bv.w;
            acc[1][0] += av.y * bv.x; acc[1][1] += av.y * bv.y; acc[1][2] += av.y * bv.z; acc[1][3] += av.y * bv.w;
            acc[2][0] += av.z * bv.x; acc[2][1] += av.z * bv.y; acc[2][2] += av.z * bv.z; acc[2][3] += av.z * bv.w;
            acc[3][0] += av.w * bv.x; acc[3][1] += av.w * bv.y; acc[3][2] += av.w * bv.z; acc[3][3] += av.w * bv.w;
        }
    }

    float bb[4], as4[4], ad4[4];
#pragma unroll
    for (int j = 0; j < 4; j++) {
        bb[j]  = b[h * FOUT + tx * 4 + j];
        as4[j] = att[h * 2 * FOUT + tx * 4 + j];
        ad4[j] = att[h * 2 * FOUT + FOUT + tx * 4 + j];
    }
    float hv[4][4];
#pragma unroll
    for (int i = 0; i < 4; i++) {
        int n = n0 + ty * 4 + i;
        float s = 0.f, d = 0.f;
#pragma unroll
        for (int j = 0; j < 4; j++) {
            hv[i][j] = acc[i][j] + bb[j];
            s += hv[i][j] * as4[j];
            d += hv[i][j] * ad4[j];
        }
#pragma unroll
        for (int off = 8; off > 0; off >>= 1) {
            s += __shfl_xor_sync(0xffffffffu, s, off);
            d += __shfl_xor_sync(0xffffffffu, d, off);
        }
        if (tx == 0) {
            g_EF[h * NN + n] = make_float2(__expf(d), __expf(0.01f * d));
            g_G[h * NN + n]  = __expf(-0.99f * s);
        }
    }
    // write H TRANSPOSED as fp16: g_HT[h][o][m], 4 consecutive m per store
#pragma unroll
    for (int j = 0; j < 4; j++) {
        unsigned lo = pk2(hv[0][j], hv[1][j]);
        unsigned hi = pk2(hv[2][j], hv[3][j]);
        *(uint2*)&g_HT[(h * FOUT + tx * 4 + j) * NN + n0 + ty * 4] = make_uint2(lo, hi);
    }
}

// ---------------------------------------------------------------------------
// Kernel 2: fp16 tensor-core PV.  p = adj * max(E_m, F_m*G_n)  (exact
// leaky_relu branch select). l via ones-column MMA. B fragments via
// ldmatrix.x4 from transposed H tile.
// block = 256 thr (8 warps x 16 rows); grid (32, MSPLIT, HEADS)
// ---------------------------------------------------------------------------
__global__ void __launch_bounds__(256) k_attn() {
    __shared__ __align__(16) __half HsT[FOUT][HSTRIDE];  // [o][m-half]
    __shared__ uint2    dEF2s[MTILE / 2];                // {E2, F2} fp16x2 pairs
    __shared__ unsigned maskS[RPB][MTILE / 32];

    const int h  = blockIdx.z;
    const int sp = blockIdx.y;
    const int n0 = blockIdx.x * RPB;
    const int t  = threadIdx.x;
    const int warp = t >> 5, lane = t & 31;
    const int g = lane >> 2, tt = lane & 3;
    const int wrow = warp * 16;
    const unsigned ONES2 = 0x3C003C00u;

    const int r8 = lane & 7, q = lane >> 3;
    const unsigned lds_base =
        smem_u32(&HsT[(q >> 1) * 8 + r8][(q & 1) * 8]);

    unsigned G2u[2];
#pragma unroll
    for (int j = 0; j < 2; j++) {
        float gv = g_G[h * NN + n0 + wrow + g + 8 * j];
        G2u[j] = pk2(gv, gv);
    }

    float cacc[8][4] = {};
    float lacc[4] = {0.f, 0.f, 0.f, 0.f};

    const int mbase = sp * (NN / MSPLIT);

    for (int mt = 0; mt < NN / MSPLIT; mt += MTILE) {
        const int mb = mbase + mt;
        __syncthreads();
#pragma unroll
        for (int u = 0; u < 4; u++) {
            int id = t + 256 * u;
            int o = id >> 4, seg = id & 15;
            *(uint4*)&HsT[o][seg * 8] =
                *(const uint4*)&g_HT[(h * FOUT + o) * NN + mb + seg * 8];
        }
        if (t < 64) {
            float2 v0 = g_EF[h * NN + mb + 2 * t];
            float2 v1 = g_EF[h * NN + mb + 2 * t + 1];
            dEF2s[t] = make_uint2(pk2(v0.x, v1.x), pk2(v0.y, v1.y));
        }
        if (t < RPB)
            *(uint4*)&maskS[t][0] =
                *(const uint4*)&g_mask[(n0 + t) * (NN / 32) + (mb >> 5)];
        __syncthreads();

#pragma unroll
        for (int cc = 0; cc < 8; cc++) {
            const uint2 ef0 = dEF2s[cc * 8 + tt];
            const uint2 ef1 = dEF2s[cc * 8 + tt + 4];
            unsigned pa[4];
#pragma unroll
            for (int j = 0; j < 2; j++) {
                unsigned w = maskS[wrow + g + 8 * j][cc >> 1];
                unsigned nib = (w >> (((cc & 1) << 4) + (tt << 2))) & 0xFu;
                unsigned am0 = (nib & 1u) * 0x3C00u + (nib & 2u) * 0x1E000000u;
                unsigned am1 = (nib & 4u) * 0x0F00u + (nib & 8u) * 0x07800000u;
                pa[j]     = hmul2u(hmax2u(ef0.x, hmul2u(ef0.y, G2u[j])), am0);
                pa[2 + j] = hmul2u(hmax2u(ef1.x, hmul2u(ef1.y, G2u[j])), am1);
            }
#pragma unroll
            for (int jp = 0; jp < 4; jp++) {
                unsigned b0, b1, b2, b3;
                unsigned addr = lds_base + jp * (16 * HSTRIDE * 2) + cc * 32;
                asm volatile(
                    "ldmatrix.sync.aligned.m8n8.x4.shared.b16 {%0,%1,%2,%3}, [%4];"
                    : "=r"(b0), "=r"(b1), "=r"(b2), "=r"(b3) : "r"(addr));
                mma_f16(cacc[2 * jp],     pa, b0, b1);
                mma_f16(cacc[2 * jp + 1], pa, b2, b3);
            }
            mma_f16(lacc, pa, ONES2, ONES2);
        }
    }

    const int base = (h * MSPLIT + sp) * NN;
    if (tt == 0) {
        g_l[base + n0 + wrow + g]     = lacc[0];
        g_l[base + n0 + wrow + g + 8] = lacc[2];
    }
    const float S = 1.0f / 32.0f;
    const int r0 = base + n0 + wrow + g;
#pragma unroll
    for (int jc = 0; jc < 8; jc++) {
        g_numh[r0 * (FOUT / 2) + jc * 4 + tt] = pk2(cacc[jc][0] * S, cacc[jc][1] * S);
        g_numh[(r0 + 8) * (FOUT / 2) + jc * 4 + tt] = pk2(cacc[jc][2] * S, cacc[jc][3] * S);
    }
}

// ---------------------------------------------------------------------------
// Kernel 3: combine m-splits and heads
// ---------------------------------------------------------------------------
__global__ void k_comb(float* __restrict__ out) {
    const int t = blockIdx.x * 256 + threadIdx.x;
    const int n = t >> 4;
    const int qc = t & 15;
    float4 r = make_float4(0.f, 0.f, 0.f, 0.f);
#pragma unroll
    for (int h = 0; h < HEADS; h++) {
        float l = 0.0f;
        float4 acc = make_float4(0.f, 0.f, 0.f, 0.f);
#pragma unroll
        for (int sp = 0; sp < MSPLIT; sp++) {
            const int row = (h * MSPLIT + sp) * NN + n;
            l += g_l[row];
            uint2 v = *(const uint2*)&g_numh[row * (FOUT / 2) + qc * 2];
            float2 lo = __half22float2(*(__half2*)&v.x);
            float2 hi = __half22float2(*(__half2*)&v.y);
            acc.x += lo.x; acc.y += lo.y; acc.z += hi.x; acc.w += hi.y;
        }
        float inv = 32.0f / l;
        r.x += acc.x * inv; r.y += acc.y * inv; r.z += acc.z * inv; r.w += acc.w * inv;
    }
    r.x *= 0.25f; r.y *= 0.25f; r.z *= 0.25f; r.w *= 0.25f;
    *(float4*)&out[n * FOUT + qc * 4] = r;
}

extern "C" void kernel_launch(void* const* d_in, const int* in_sizes, int n_in,
                              void* d_out, int out_size) {
    const float* X   = (const float*)d_in[0];
    const int*   A   = (const int*)d_in[1];
    const float* W   = (const float*)d_in[2];
    const float* b   = (const float*)d_in[3];
    const float* att = (const float*)d_in[4];
    float* out = (float*)d_out;

    k_pp<<<256 + NN / 4, 256>>>(A, X, W, b, att);
    k_attn<<<dim3(NN / RPB, MSPLIT, HEADS), 256>>>();
    k_comb<<<(NN * FOUT / 4) / 256, 256>>>(out);
}

// round 14
// speedup vs baseline: 1.0222x; 1.0222x over previous
#include <cuda_runtime.h>
#include <cuda_fp16.h>

#define NN 4096
#define FIN 128
#define FOUT 64
#define HEADS 4
#define MSPLIT 4
#define RPB 128          // n-rows per block in k_attn
#define MTILE 128        // m per smem tile
#define HSTRIDE 136      // halves per HsT row (128 + 8 pad -> LDSM conflict-free)

// Device scratch (allocation-free rule: __device__ globals)
__device__ __half   g_HT[HEADS * FOUT * NN];         // H transposed: [h][o][m] fp16
__device__ float2   g_EF[HEADS * NN];                // {exp(d), exp(0.01d)}
__device__ float    g_G[HEADS * NN];                 // exp(-0.99 s)
__device__ unsigned g_mask[NN * (NN / 32)];          // bit-packed A|diag, MMA-permuted
__device__ unsigned g_numh[HEADS * MSPLIT * NN * (FOUT / 2)];  // fp16x2, scaled 1/32
__device__ float    g_l[HEADS * MSPLIT * NN];

__device__ __forceinline__ unsigned hmul2u(unsigned a, unsigned b) {
    __half2 r = __hmul2(*(__half2*)&a, *(__half2*)&b);
    return *(unsigned*)&r;
}
__device__ __forceinline__ unsigned hmax2u(unsigned a, unsigned b) {
    __half2 r = __hmax2(*(__half2*)&a, *(__half2*)&b);
    return *(unsigned*)&r;
}
__device__ __forceinline__ unsigned pk2(float lo, float hi) {
    __half2 r = __floats2half2_rn(lo, hi);
    return *(unsigned*)&r;
}
__device__ __forceinline__ unsigned smem_u32(const void* p) {
    return (unsigned)__cvta_generic_to_shared(p);
}

__device__ __forceinline__ void mma_f16(float c[4], const unsigned a[4],
                                        unsigned b0, unsigned b1) {
    asm volatile(
        "mma.sync.aligned.m16n8k16.row.col.f32.f16.f16.f32 "
        "{%0,%1,%2,%3}, {%4,%5,%6,%7}, {%8,%9}, {%0,%1,%2,%3};\n"
        : "+f"(c[0]), "+f"(c[1]), "+f"(c[2]), "+f"(c[3])
        : "r"(a[0]), "r"(a[1]), "r"(a[2]), "r"(a[3]), "r"(b0), "r"(b1));
}

// ---------------------------------------------------------------------------
// Kernel 0: STANDALONE adjacency bit-pack. No smem, low regs -> 8 blocks/SM,
// 64 warps/SM of pure stream (TLP-saturated). One row per block; warp-
// coalesced int4 loads (MLP=4); A in {0,1} so value IS the bit.
// Bit layout identical to prior rounds:
// word bit (16hh+4tt+dd) = adjacency col (16hh + 2tt + (dd&1) + 8*(dd>>1)).
// ---------------------------------------------------------------------------
__global__ void __launch_bounds__(256) k_pack(const int* __restrict__ A) {
    const int row  = blockIdx.x;
    const int t    = threadIdx.x;
    const int warp = t >> 5, lane = t & 31;
    const int j    = lane & 7;
    const int w    = lane >> 3;
    const int base = 16 * (j >> 2) + 8 * (j & 1) + 2 * ((j >> 1) & 1);
    const unsigned submask = 0xFFu << (w << 3);

    int4 a4[4];
#pragma unroll
    for (int it = 0; it < 4; it++)
        a4[it] = *(const int4*)&A[row * NN + (it * 8 + warp) * 128 + lane * 4];

#pragma unroll
    for (int it = 0; it < 4; it++) {
        const int chunk = it * 8 + warp;
        unsigned v01 = (unsigned)a4[it].x + ((unsigned)a4[it].y << 1);
        unsigned v23 = (unsigned)a4[it].z + ((unsigned)a4[it].w << 1);
        unsigned contrib = (v01 + (v23 << 4)) << base;
        unsigned word = __reduce_or_sync(submask, contrib);
        if (j == 0) {
            const int widx = chunk * 4 + w;
            if (widx == (row >> 5)) {              // diagonal lives in this word
                const int c = row & 31;
                word |= 1u << (16 * (c >> 4) + 4 * ((c & 7) >> 1)
                               + 2 * ((c >> 3) & 1) + (c & 1));
            }
            g_mask[row * (NN / 32) + widx] = word;
        }
    }
}

// ---------------------------------------------------------------------------
// Kernel 1: projection + fused per-node scores/exp factors (standalone).
// Transposed smem tiles -> conflict-free LDS.128.
// ---------------------------------------------------------------------------
__global__ void __launch_bounds__(256) k_proj(const float* __restrict__ X,
                                              const float* __restrict__ W,
                                              const float* __restrict__ b,
                                              const float* __restrict__ att) {
    __shared__ __align__(16) float XsT[64][68];   // [k][n-row]
    __shared__ __align__(16) float WsT[64][68];   // [k][o-row]
    const int t  = threadIdx.x;
    const int h  = blockIdx.x >> 6;
    const int n0 = (blockIdx.x & 63) * 64;
    const int ty = t >> 4, tx = t & 15;

    float acc[4][4] = {};

    for (int kc = 0; kc < FIN; kc += 64) {
        __syncthreads();
#pragma unroll
        for (int u = 0; u < 4; u++) {
            int idx = t + 256 * u;
            int r = idx >> 4, q = (idx & 15) * 4;
            float4 xv = *(const float4*)&X[(n0 + r) * FIN + kc + q];
            XsT[q + 0][r] = xv.x; XsT[q + 1][r] = xv.y;
            XsT[q + 2][r] = xv.z; XsT[q + 3][r] = xv.w;
            float4 wv = *(const float4*)&W[(h * FOUT + r) * FIN + kc + q];
            WsT[q + 0][r] = wv.x; WsT[q + 1][r] = wv.y;
            WsT[q + 2][r] = wv.z; WsT[q + 3][r] = wv.w;
        }
        __syncthreads();
#pragma unroll 8
        for (int k = 0; k < 64; k++) {
            float4 av = *(const float4*)&XsT[k][ty * 4];
            float4 bv = *(const float4*)&WsT[k][tx * 4];
            acc[0][0] += av.x * bv.x; acc[0][1] += av.x * bv.y; acc[0][2] += av.x * bv.z; acc[0][3] += av.x * bv.w;
            acc[1][0] += av.y * bv.x; acc[1][1] += av.y * bv.y; acc[1][2] += av.y * bv.z; acc[1][3] += av.y * bv.w;
            acc[2][0] += av.z * bv.x; acc[2][1] += av.z * bv.y; acc[2][2] += av.z * bv.z; acc[2][3] += av.z * bv.w;
            acc[3][0] += av.w * bv.x; acc[3][1] += av.w * bv.y; acc[3][2] += av.w * bv.z; acc[3][3] += av.w * bv.w;
        }
    }

    float bb[4], as4[4], ad4[4];
#pragma unroll
    for (int j = 0; j < 4; j++) {
        bb[j]  = b[h * FOUT + tx * 4 + j];
        as4[j] = att[h * 2 * FOUT + tx * 4 + j];
        ad4[j] = att[h * 2 * FOUT + FOUT + tx * 4 + j];
    }
    float hv[4][4];
#pragma unroll
    for (int i = 0; i < 4; i++) {
        int n = n0 + ty * 4 + i;
        float s = 0.f, d = 0.f;
#pragma unroll
        for (int j = 0; j < 4; j++) {
            hv[i][j] = acc[i][j] + bb[j];
            s += hv[i][j] * as4[j];
            d += hv[i][j] * ad4[j];
        }
#pragma unroll
        for (int off = 8; off > 0; off >>= 1) {
            s += __shfl_xor_sync(0xffffffffu, s, off);
            d += __shfl_xor_sync(0xffffffffu, d, off);
        }
        if (tx == 0) {
            g_EF[h * NN + n] = make_float2(__expf(d), __expf(0.01f * d));
            g_G[h * NN + n]  = __expf(-0.99f * s);
        }
    }
    // write H TRANSPOSED as fp16: g_HT[h][o][m], 4 consecutive m per store
#pragma unroll
    for (int j = 0; j < 4; j++) {
        unsigned lo = pk2(hv[0][j], hv[1][j]);
        unsigned hi = pk2(hv[2][j], hv[3][j]);
        *(uint2*)&g_HT[(h * FOUT + tx * 4 + j) * NN + n0 + ty * 4] = make_uint2(lo, hi);
    }
}

// ---------------------------------------------------------------------------
// Kernel 2: fp16 tensor-core PV.  p = adj * max(E_m, F_m*G_n)  (exact
// leaky_relu branch select). l via ones-column MMA. B fragments via
// ldmatrix.x4 from transposed H tile.
// block = 256 thr (8 warps x 16 rows); grid (32, MSPLIT, HEADS)
// ---------------------------------------------------------------------------
__global__ void __launch_bounds__(256) k_attn() {
    __shared__ __align__(16) __half HsT[FOUT][HSTRIDE];  // [o][m-half]
    __shared__ uint2    dEF2s[MTILE / 2];                // {E2, F2} fp16x2 pairs
    __shared__ unsigned maskS[RPB][MTILE / 32];

    const int h  = blockIdx.z;
    const int sp = blockIdx.y;
    const int n0 = blockIdx.x * RPB;
    const int t  = threadIdx.x;
    const int warp = t >> 5, lane = t & 31;
    const int g = lane >> 2, tt = lane & 3;
    const int wrow = warp * 16;
    const unsigned ONES2 = 0x3C003C00u;

    const int r8 = lane & 7, q = lane >> 3;
    const unsigned lds_base =
        smem_u32(&HsT[(q >> 1) * 8 + r8][(q & 1) * 8]);

    unsigned G2u[2];
#pragma unroll
    for (int j = 0; j < 2; j++) {
        float gv = g_G[h * NN + n0 + wrow + g + 8 * j];
        G2u[j] = pk2(gv, gv);
    }

    float cacc[8][4] = {};
    float lacc[4] = {0.f, 0.f, 0.f, 0.f};

    const int mbase = sp * (NN / MSPLIT);

    for (int mt = 0; mt < NN / MSPLIT; mt += MTILE) {
        const int mb = mbase + mt;
        __syncthreads();
#pragma unroll
        for (int u = 0; u < 4; u++) {
            int id = t + 256 * u;
            int o = id >> 4, seg = id & 15;
            *(uint4*)&HsT[o][seg * 8] =
                *(const uint4*)&g_HT[(h * FOUT + o) * NN + mb + seg * 8];
        }
        if (t < 64) {
            float2 v0 = g_EF[h * NN + mb + 2 * t];
            float2 v1 = g_EF[h * NN + mb + 2 * t + 1];
            dEF2s[t] = make_uint2(pk2(v0.x, v1.x), pk2(v0.y, v1.y));
        }
        if (t < RPB)
            *(uint4*)&maskS[t][0] =
                *(const uint4*)&g_mask[(n0 + t) * (NN / 32) + (mb >> 5)];
        __syncthreads();

#pragma unroll
        for (int cc = 0; cc < 8; cc++) {
            const uint2 ef0 = dEF2s[cc * 8 + tt];
            const uint2 ef1 = dEF2s[cc * 8 + tt + 4];
            unsigned pa[4];
#pragma unroll
            for (int j = 0; j < 2; j++) {
                unsigned w = maskS[wrow + g + 8 * j][cc >> 1];
                unsigned nib = (w >> (((cc & 1) << 4) + (tt << 2))) & 0xFu;
                unsigned am0 = (nib & 1u) * 0x3C00u + (nib & 2u) * 0x1E000000u;
                unsigned am1 = (nib & 4u) * 0x0F00u + (nib & 8u) * 0x07800000u;
                pa[j]     = hmul2u(hmax2u(ef0.x, hmul2u(ef0.y, G2u[j])), am0);
                pa[2 + j] = hmul2u(hmax2u(ef1.x, hmul2u(ef1.y, G2u[j])), am1);
            }
#pragma unroll
            for (int jp = 0; jp < 4; jp++) {
                unsigned b0, b1, b2, b3;
                unsigned addr = lds_base + jp * (16 * HSTRIDE * 2) + cc * 32;
                asm volatile(
                    "ldmatrix.sync.aligned.m8n8.x4.shared.b16 {%0,%1,%2,%3}, [%4];"
                    : "=r"(b0), "=r"(b1), "=r"(b2), "=r"(b3) : "r"(addr));
                mma_f16(cacc[2 * jp],     pa, b0, b1);
                mma_f16(cacc[2 * jp + 1], pa, b2, b3);
            }
            mma_f16(lacc, pa, ONES2, ONES2);
        }
    }

    const int base = (h * MSPLIT + sp) * NN;
    if (tt == 0) {
        g_l[base + n0 + wrow + g]     = lacc[0];
        g_l[base + n0 + wrow + g + 8] = lacc[2];
    }
    const float S = 1.0f / 32.0f;
    const int r0 = base + n0 + wrow + g;
#pragma unroll
    for (int jc = 0; jc < 8; jc++) {
        g_numh[r0 * (FOUT / 2) + jc * 4 + tt] = pk2(cacc[jc][0] * S, cacc[jc][1] * S);
        g_numh[(r0 + 8) * (FOUT / 2) + jc * 4 + tt] = pk2(cacc[jc][2] * S, cacc[jc][3] * S);
    }
}

// ---------------------------------------------------------------------------
// Kernel 3: combine m-splits and heads
// ---------------------------------------------------------------------------
__global__ void k_comb(float* __restrict__ out) {
    const int t = blockIdx.x * 256 + threadIdx.x;
    const int n = t >> 4;
    const int qc = t & 15;
    float4 r = make_float4(0.f, 0.f, 0.f, 0.f);
#pragma unroll
    for (int h = 0; h < HEADS; h++) {
        float l = 0.0f;
        float4 acc = make_float4(0.f, 0.f, 0.f, 0.f);
#pragma unroll
        for (int sp = 0; sp < MSPLIT; sp++) {
            const int row = (h * MSPLIT + sp) * NN + n;
            l += g_l[row];
            uint2 v = *(const uint2*)&g_numh[row * (FOUT / 2) + qc * 2];
            float2 lo = __half22float2(*(__half2*)&v.x);
            float2 hi = __half22float2(*(__half2*)&v.y);
            acc.x += lo.x; acc.y += lo.y; acc.z += hi.x; acc.w += hi.y;
        }
        float inv = 32.0f / l;
        r.x += acc.x * inv; r.y += acc.y * inv; r.z += acc.z * inv; r.w += acc.w * inv;
    }
    r.x *= 0.25f; r.y *= 0.25f; r.z *= 0.25f; r.w *= 0.25f;
    *(float4*)&out[n * FOUT + qc * 4] = r;
}

extern "C" void kernel_launch(void* const* d_in, const int* in_sizes, int n_in,
                              void* d_out, int out_size) {
    const float* X   = (const float*)d_in[0];
    const int*   A   = (const int*)d_in[1];
    const float* W   = (const float*)d_in[2];
    const float* b   = (const float*)d_in[3];
    const float* att = (const float*)d_in[4];
    float* out = (float*)d_out;

    k_pack<<<NN, 256>>>(A);
    k_proj<<<256, 256>>>(X, W, b, att);
    k_attn<<<dim3(NN / RPB, MSPLIT, HEADS), 256>>>();
    k_comb<<<(NN * FOUT / 4) / 256, 256>>>(out);
}

// round 16
// speedup vs baseline: 1.0837x; 1.0602x over previous
#include <cuda_runtime.h>
#include <cuda_fp16.h>

#define NN 4096
#define FIN 128
#define FOUT 64
#define HEADS 4
#define MSPLIT 4
#define RPB 128          // n-rows per block in k_attn
#define MTILE 128        // m per smem tile
#define HSTRIDE 136      // halves per HsT row (128 + 8 pad -> LDSM conflict-free)

// Device scratch (allocation-free rule: __device__ globals)
__device__ __half   g_HT[HEADS * FOUT * NN];         // H transposed: [h][o][m] fp16
__device__ float2   g_EF[HEADS * NN];                // {exp(d), exp(0.01d)}
__device__ float    g_G[HEADS * NN];                 // exp(-0.99 s)
__device__ unsigned g_mask[NN * (NN / 32)];          // bit-packed A|diag, MMA-permuted
__device__ unsigned g_numh[HEADS * MSPLIT * NN * (FOUT / 2)];  // fp16x2, scaled 1/32
__device__ float    g_l[HEADS * MSPLIT * NN];

__device__ __forceinline__ unsigned hmul2u(unsigned a, unsigned b) {
    __half2 r = __hmul2(*(__half2*)&a, *(__half2*)&b);
    return *(unsigned*)&r;
}
__device__ __forceinline__ unsigned hmax2u(unsigned a, unsigned b) {
    __half2 r = __hmax2(*(__half2*)&a, *(__half2*)&b);
    return *(unsigned*)&r;
}
__device__ __forceinline__ unsigned pk2(float lo, float hi) {
    __half2 r = __floats2half2_rn(lo, hi);
    return *(unsigned*)&r;
}
__device__ __forceinline__ unsigned smem_u32(const void* p) {
    return (unsigned)__cvta_generic_to_shared(p);
}

__device__ __forceinline__ void mma_f16(float c[4], const unsigned a[4],
                                        unsigned b0, unsigned b1) {
    asm volatile(
        "mma.sync.aligned.m16n8k16.row.col.f32.f16.f16.f32 "
        "{%0,%1,%2,%3}, {%4,%5,%6,%7}, {%8,%9}, {%0,%1,%2,%3};\n"
        : "+f"(c[0]), "+f"(c[1]), "+f"(c[2]), "+f"(c[3])
        : "r"(a[0]), "r"(a[1]), "r"(a[2]), "r"(a[3]), "r"(b0), "r"(b1));
}

// ---------------------------------------------------------------------------
// Kernel 1: merged projection (blocks 0..255) + adjacency bit-pack (blocks
// 256..). Pack exploits A in {0,1}: the int32 value IS the adjacency bit
// (3 IMAD + shift per int4, no predicates). Diagonal OR'd scalar-side at
// store. Bit layout (MMA-permuted):
// word bit (16hh+4tt+dd) = adjacency col (16hh + 2tt + (dd&1) + 8*(dd>>1)).
// ---------------------------------------------------------------------------
__global__ void __launch_bounds__(256) k_pp(const int* __restrict__ A,
                                            const float* __restrict__ X,
                                            const float* __restrict__ W,
                                            const float* __restrict__ b,
                                            const float* __restrict__ att) {
    __shared__ __align__(16) float XsT[64][68];   // [k][n-row]
    __shared__ __align__(16) float WsT[64][68];   // [k][o-row]
    const int t = threadIdx.x;

    if (blockIdx.x >= 256) {
        const int row  = blockIdx.x - 256;
        const int warp = t >> 5, lane = t & 31;
        const int j    = lane & 7;
        const int w    = lane >> 3;
        const int base = 16 * (j >> 2) + 8 * (j & 1) + 2 * ((j >> 1) & 1);
        const unsigned submask = 0xFFu << (w << 3);

        // issue ALL loads first (independent -> MLP=4)
        int4 a4[4];
#pragma unroll
        for (int it = 0; it < 4; it++)
            a4[it] = *(const int4*)&A[row * NN + (it * 8 + warp) * 128 + lane * 4];

#pragma unroll
        for (int it = 0; it < 4; it++) {
            const int chunk = it * 8 + warp;
            unsigned v01 = (unsigned)a4[it].x + ((unsigned)a4[it].y << 1);
            unsigned v23 = (unsigned)a4[it].z + ((unsigned)a4[it].w << 1);
            unsigned contrib = (v01 + (v23 << 4)) << base;
            unsigned word = __reduce_or_sync(submask, contrib);
            if (j == 0) {
                const int widx = chunk * 4 + w;
                if (widx == (row >> 5)) {          // diagonal lives in this word
                    const int c = row & 31;
                    word |= 1u << (16 * (c >> 4) + 4 * ((c & 7) >> 1)
                                   + 2 * ((c >> 3) & 1) + (c & 1));
                }
                g_mask[row * (NN / 32) + widx] = word;
            }
        }
        return;
    }

    // ---------------- projection + fused scores/exp factors ----------------
    const int h  = blockIdx.x >> 6;
    const int n0 = (blockIdx.x & 63) * 64;
    const int ty = t >> 4, tx = t & 15;

    float acc[4][4] = {};

    for (int kc = 0; kc < FIN; kc += 64) {
        __syncthreads();
#pragma unroll
        for (int u = 0; u < 4; u++) {
            int idx = t + 256 * u;
            int r = idx >> 4, q = (idx & 15) * 4;
            float4 xv = *(const float4*)&X[(n0 + r) * FIN + kc + q];
            XsT[q + 0][r] = xv.x; XsT[q + 1][r] = xv.y;
            XsT[q + 2][r] = xv.z; XsT[q + 3][r] = xv.w;
            float4 wv = *(const float4*)&W[(h * FOUT + r) * FIN + kc + q];
            WsT[q + 0][r] = wv.x; WsT[q + 1][r] = wv.y;
            WsT[q + 2][r] = wv.z; WsT[q + 3][r] = wv.w;
        }
        __syncthreads();
#pragma unroll 8
        for (int k = 0; k < 64; k++) {
            float4 av = *(const float4*)&XsT[k][ty * 4];
            float4 bv = *(const float4*)&WsT[k][tx * 4];
            acc[0][0] += av.x * bv.x; acc[0][1] += av.x * bv.y; acc[0][2] += av.x * bv.z; acc[0][3] += av.x * bv.w;
            acc[1][0] += av.y * bv.x; acc[1][1] += av.y * bv.y; acc[1][2] += av.y * bv.z; acc[1][3] += av.y * bv.w;
            acc[2][0] += av.z * bv.x; acc[2][1] += av.z * bv.y; acc[2][2] += av.z * bv.z; acc[2][3] += av.z * bv.w;
            acc[3][0] += av.w * bv.x; acc[3][1] += av.w * bv.y; acc[3][2] += av.w * bv.z; acc[3][3] += av.w * bv.w;
        }
    }

    float bb[4], as4[4], ad4[4];
#pragma unroll
    for (int j = 0; j < 4; j++) {
        bb[j]  = b[h * FOUT + tx * 4 + j];
        as4[j] = att[h * 2 * FOUT + tx * 4 + j];
        ad4[j] = att[h * 2 * FOUT + FOUT + tx * 4 + j];
    }
    float hv[4][4];
#pragma unroll
    for (int i = 0; i < 4; i++) {
        int n = n0 + ty * 4 + i;
        float s = 0.f, d = 0.f;
#pragma unroll
        for (int j = 0; j < 4; j++) {
            hv[i][j] = acc[i][j] + bb[j];
            s += hv[i][j] * as4[j];
            d += hv[i][j] * ad4[j];
        }
#pragma unroll
        for (int off = 8; off > 0; off >>= 1) {
            s += __shfl_xor_sync(0xffffffffu, s, off);
            d += __shfl_xor_sync(0xffffffffu, d, off);
        }
        if (tx == 0) {
            g_EF[h * NN + n] = make_float2(__expf(d), __expf(0.01f * d));
            g_G[h * NN + n]  = __expf(-0.99f * s);
        }
    }
    // write H TRANSPOSED as fp16: g_HT[h][o][m], 4 consecutive m per store
#pragma unroll
    for (int j = 0; j < 4; j++) {
        unsigned lo = pk2(hv[0][j], hv[1][j]);
        unsigned hi = pk2(hv[2][j], hv[3][j]);
        *(uint2*)&g_HT[(h * FOUT + tx * 4 + j) * NN + n0 + ty * 4] = make_uint2(lo, hi);
    }
}

// ---------------------------------------------------------------------------
// Kernel 2: fp16 tensor-core PV.  p = adj * max(E_m, F_m*G_n)  (exact
// leaky_relu branch select). l via ones-column MMA. B fragments via
// ldmatrix.x4. REGISTER-PREFETCH double buffering: next tile's global loads
// are issued right after the smem stores, completing under the compute phase.
// block = 256 thr (8 warps x 16 rows); grid (32, MSPLIT, HEADS)
// ---------------------------------------------------------------------------
__global__ void __launch_bounds__(256) k_attn() {
    __shared__ __align__(16) __half HsT[FOUT][HSTRIDE];  // [o][m-half]
    __shared__ uint2    dEF2s[MTILE / 2];                // {E2, F2} fp16x2 pairs
    __shared__ unsigned maskS[RPB][MTILE / 32];

    const int h  = blockIdx.z;
    const int sp = blockIdx.y;
    const int n0 = blockIdx.x * RPB;
    const int t  = threadIdx.x;
    const int warp = t >> 5, lane = t & 31;
    const int g = lane >> 2, tt = lane & 3;
    const int wrow = warp * 16;
    const unsigned ONES2 = 0x3C003C00u;

    const int r8 = lane & 7, q = lane >> 3;
    const unsigned lds_base =
        smem_u32(&HsT[(q >> 1) * 8 + r8][(q & 1) * 8]);

    unsigned G2u[2];
#pragma unroll
    for (int j = 0; j < 2; j++) {
        float gv = g_G[h * NN + n0 + wrow + g + 8 * j];
        G2u[j] = pk2(gv, gv);
    }

    float cacc[8][4] = {};
    float lacc[4] = {0.f, 0.f, 0.f, 0.f};

    const int mbase = sp * (NN / MSPLIT);
    const int ho = t >> 4, seg = t & 15;     // staging decomposition (u-strided)

    // ---- prefetch registers ----
    uint4 hreg[4];
    float2 ef0r, ef1r;
    uint4 mreg;

    auto ldtile = [&](int mb) {
#pragma unroll
        for (int u = 0; u < 4; u++) {
            int o = ho + u * 16;
            hreg[u] = *(const uint4*)&g_HT[(h * FOUT + o) * NN + mb + seg * 8];
        }
        if (t < 64) {
            ef0r = g_EF[h * NN + mb + 2 * t];
            ef1r = g_EF[h * NN + mb + 2 * t + 1];
        }
        if (t < RPB)
            mreg = *(const uint4*)&g_mask[(n0 + t) * (NN / 32) + (mb >> 5)];
    };

    ldtile(mbase);                            // tile 0

    for (int tile = 0; tile < NN / MSPLIT / MTILE; tile++) {
        __syncthreads();                      // previous compute done
        // store prefetched tile to smem
#pragma unroll
        for (int u = 0; u < 4; u++)
            *(uint4*)&HsT[ho + u * 16][seg * 8] = hreg[u];
        if (t < 64)
            dEF2s[t] = make_uint2(pk2(ef0r.x, ef1r.x), pk2(ef0r.y, ef1r.y));
        if (t < RPB)
            *(uint4*)&maskS[t][0] = mreg;
        __syncthreads();

        // issue next tile's loads NOW (hidden under compute below)
        if (tile + 1 < NN / MSPLIT / MTILE)
            ldtile(mbase + (tile + 1) * MTILE);

#pragma unroll
        for (int cc = 0; cc < 8; cc++) {
            const uint2 ef0 = dEF2s[cc * 8 + tt];
            const uint2 ef1 = dEF2s[cc * 8 + tt + 4];
            unsigned pa[4];
#pragma unroll
            for (int j = 0; j < 2; j++) {
                unsigned w = maskS[wrow + g + 8 * j][cc >> 1];
                unsigned nib = (w >> (((cc & 1) << 4) + (tt << 2))) & 0xFu;
                unsigned am0 = (nib & 1u) * 0x3C00u + (nib & 2u) * 0x1E000000u;
                unsigned am1 = (nib & 4u) * 0x0F00u + (nib & 8u) * 0x07800000u;
                pa[j]     = hmul2u(hmax2u(ef0.x, hmul2u(ef0.y, G2u[j])), am0);
                pa[2 + j] = hmul2u(hmax2u(ef1.x, hmul2u(ef1.y, G2u[j])), am1);
            }
#pragma unroll
            for (int jp = 0; jp < 4; jp++) {
                unsigned b0, b1, b2, b3;
                unsigned addr = lds_base + jp * (16 * HSTRIDE * 2) + cc * 32;
                asm volatile(
                    "ldmatrix.sync.aligned.m8n8.x4.shared.b16 {%0,%1,%2,%3}, [%4];"
                    : "=r"(b0), "=r"(b1), "=r"(b2), "=r"(b3) : "r"(addr));
                mma_f16(cacc[2 * jp],     pa, b0, b1);
                mma_f16(cacc[2 * jp + 1], pa, b2, b3);
            }
            mma_f16(lacc, pa, ONES2, ONES2);
        }
    }

    const int base = (h * MSPLIT + sp) * NN;
    if (tt == 0) {
        g_l[base + n0 + wrow + g]     = lacc[0];
        g_l[base + n0 + wrow + g + 8] = lacc[2];
    }
    const float S = 1.0f / 32.0f;
    const int r0 = base + n0 + wrow + g;
#pragma unroll
    for (int jc = 0; jc < 8; jc++) {
        g_numh[r0 * (FOUT / 2) + jc * 4 + tt] = pk2(cacc[jc][0] * S, cacc[jc][1] * S);
        g_numh[(r0 + 8) * (FOUT / 2) + jc * 4 + tt] = pk2(cacc[jc][2] * S, cacc[jc][3] * S);
    }
}

// ---------------------------------------------------------------------------
// Kernel 3: combine m-splits and heads. One float2 per thread (doubles
// resident warps vs float4 -> hides latency; loads stay fully coalesced).
// ---------------------------------------------------------------------------
__global__ void k_comb(float* __restrict__ out) {
    const int t = blockIdx.x * 256 + threadIdx.x;   // 0 .. NN*FOUT/2-1
    const int n = t >> 5;
    const int qc = t & 31;                          // column pair index
    float rx = 0.f, ry = 0.f;
#pragma unroll
    for (int h = 0; h < HEADS; h++) {
        float l = 0.0f;
        float ax = 0.f, ay = 0.f;
#pragma unroll
        for (int sp = 0; sp < MSPLIT; sp++) {
            const int row = (h * MSPLIT + sp) * NN + n;
            l += g_l[row];
            unsigned v = g_numh[row * (FOUT / 2) + qc];
            float2 lo = __half22float2(*(__half2*)&v);
            ax += lo.x; ay += lo.y;
        }
        float inv = 32.0f / l;
        rx += ax * inv; ry += ay * inv;
    }
    *(float2*)&out[n * FOUT + qc * 2] = make_float2(rx * 0.25f, ry * 0.25f);
}

extern "C" void kernel_launch(void* const* d_in, const int* in_sizes, int n_in,
                              void* d_out, int out_size) {
    const float* X   = (const float*)d_in[0];
    const int*   A   = (const int*)d_in[1];
    const float* W   = (const float*)d_in[2];
    const float* b   = (const float*)d_in[3];
    const float* att = (const float*)d_in[4];
    float* out = (float*)d_out;

    k_pp<<<256 + NN, 256>>>(A, X, W, b, att);
    k_attn<<<dim3(NN / RPB, MSPLIT, HEADS), 256>>>();
    k_comb<<<(NN * FOUT / 2) / 256, 256>>>(out);
}